// round 14
// baseline (speedup 1.0000x reference)
#include <cuda_runtime.h>

// IF (integrate-and-fire) scan. x: (B=32, T=8, CHW=200704) fp32.
// FINAL. HBM-roofline streaming kernel, held across R9/R11/R12/R13
// (identical-binary kernel samples 56.38/56.48/57.15/58.11us -> noise
// band +-1.7us; all R1-R10 policy/structure deltas are within it).
//   411MB (205.5 in + 205.5 out = information floor, fp32 out is
//   contractual, zero reuse) at ~7.2-7.3 TB/s effective bidirectional
//   (~90% of 8TB/s spec; ~78-80% dram-active = 1:1 R/W turnaround ceiling).
// Config: one float4 per thread across all 8 timesteps; 8 front-batched
// scan-independent LDG.128 (MLP=8); exact 2D grid (196,32) with no tail
// predicate or div/mod; default-policy loads; write-through stores
// (never-read output -> no L2 dirty-line allocation).
// Exhausted levers (all neutral-or-worse at the noise floor): grid
// geometry 1D/2D/persistent, block 256/512, unroll 1x/2x, load/store
// phase separation, full ld/st cache-policy matrix. Compute pipes <15%,
// issue ~12%, occupancy non-binding (54-65% gave identical bandwidth).

#define T_STEPS 8
#define BATCH 32
#define CHW4 50176              // (64*56*56)/4 float4 per timestep-slice
#define VTH 1.0f

__global__ void __launch_bounds__(256) if_scan_kernel(
    const float4* __restrict__ x, float4* __restrict__ out)
{
    const int p = blockIdx.x * 256 + threadIdx.x;     // 0 .. CHW4-1, exact
    const int b = blockIdx.y;                          // batch index
    const long long base = (long long)b * (T_STEPS * CHW4) + p;

    // Load burst: 8 independent LDG.128 (MLP=8), default policy
    float4 xt[T_STEPS];
#pragma unroll
    for (int t = 0; t < T_STEPS; t++)
        xt[t] = x[base + t * CHW4];

    float mx = 0.f, my = 0.f, mz = 0.f, mw = 0.f;
#pragma unroll
    for (int t = 0; t < T_STEPS; t++) {
        mx += xt[t].x; my += xt[t].y; mz += xt[t].z; mw += xt[t].w;
        float4 s;
        s.x = (mx > VTH) ? 1.0f : 0.0f;
        s.y = (my > VTH) ? 1.0f : 0.0f;
        s.z = (mz > VTH) ? 1.0f : 0.0f;
        s.w = (mw > VTH) ? 1.0f : 0.0f;
        mx = (mx > VTH) ? 0.0f : mx;
        my = (my > VTH) ? 0.0f : my;
        mz = (mz > VTH) ? 0.0f : mz;
        mw = (mw > VTH) ? 0.0f : mw;
        // Write-through: never-read output, no L2 dirty-line allocation.
        __stwt(out + base + t * CHW4, s);
    }
}

extern "C" void kernel_launch(void* const* d_in, const int* in_sizes, int n_in,
                              void* d_out, int out_size)
{
    const float4* x = (const float4*)d_in[0];
    float4* out = (float4*)d_out;
    dim3 grid(CHW4 / 256, BATCH, 1);   // (196, 32)
    if_scan_kernel<<<grid, 256>>>(x, out);
}

// round 15
// speedup vs baseline: 1.0140x; 1.0140x over previous
#include <cuda_runtime.h>

// IF (integrate-and-fire) scan. x: (B=32, T=8, CHW=200704) fp32.
// FINAL. HBM-roofline streaming kernel, held across R9/R11-R14
// (identical-binary kernel samples 56.38/56.48/57.09/57.15/58.11us ->
// noise band +-1.7us; all R1-R10 policy/structure deltas fall within it).
//   411MB (205.5 in + 205.5 out = information floor, fp32 out is
//   contractual, zero reuse) at ~7.2-7.3 TB/s effective bidirectional
//   (~90% of 8TB/s spec; ~78-80% dram-active = 1:1 R/W turnaround ceiling).
// Config: one float4 per thread across all 8 timesteps; 8 front-batched
// scan-independent LDG.128 (MLP=8); exact 2D grid (196,32) with no tail
// predicate or div/mod; default-policy loads; write-through stores
// (never-read output -> no L2 dirty-line allocation).
// Exhausted levers (all neutral-or-worse at the noise floor): grid
// geometry 1D/2D/persistent, block 256/512, unroll 1x/2x, load/store
// phase separation, full ld/st cache-policy matrix. Compute pipes <15%,
// issue ~12%, occupancy non-binding (54-65% gave identical bandwidth).

#define T_STEPS 8
#define BATCH 32
#define CHW4 50176              // (64*56*56)/4 float4 per timestep-slice
#define VTH 1.0f

__global__ void __launch_bounds__(256) if_scan_kernel(
    const float4* __restrict__ x, float4* __restrict__ out)
{
    const int p = blockIdx.x * 256 + threadIdx.x;     // 0 .. CHW4-1, exact
    const int b = blockIdx.y;                          // batch index
    const long long base = (long long)b * (T_STEPS * CHW4) + p;

    // Load burst: 8 independent LDG.128 (MLP=8), default policy
    float4 xt[T_STEPS];
#pragma unroll
    for (int t = 0; t < T_STEPS; t++)
        xt[t] = x[base + t * CHW4];

    float mx = 0.f, my = 0.f, mz = 0.f, mw = 0.f;
#pragma unroll
    for (int t = 0; t < T_STEPS; t++) {
        mx += xt[t].x; my += xt[t].y; mz += xt[t].z; mw += xt[t].w;
        float4 s;
        s.x = (mx > VTH) ? 1.0f : 0.0f;
        s.y = (my > VTH) ? 1.0f : 0.0f;
        s.z = (mz > VTH) ? 1.0f : 0.0f;
        s.w = (mw > VTH) ? 1.0f : 0.0f;
        mx = (mx > VTH) ? 0.0f : mx;
        my = (my > VTH) ? 0.0f : my;
        mz = (mz > VTH) ? 0.0f : mz;
        mw = (mw > VTH) ? 0.0f : mw;
        // Write-through: never-read output, no L2 dirty-line allocation.
        __stwt(out + base + t * CHW4, s);
    }
}

extern "C" void kernel_launch(void* const* d_in, const int* in_sizes, int n_in,
                              void* d_out, int out_size)
{
    const float4* x = (const float4*)d_in[0];
    float4* out = (float4*)d_out;
    dim3 grid(CHW4 / 256, BATCH, 1);   // (196, 32)
    if_scan_kernel<<<grid, 256>>>(x, out);
}